// round 1
// baseline (speedup 1.0000x reference)
#include <cuda_runtime.h>
#include <stdint.h>

#define HH 2048
#define WW 2048
#define NPIX (HH*WW)
#define HBINS 8192
#define CAP 8192
#define NMS_EPS_F 1e-5f
#define SAM_EPS_F 1e-8f

// Scratch (device globals — no allocation allowed)
__device__ float g_nms[NPIX];
__device__ unsigned int g_hist[HBINS];
__device__ unsigned long long g_cand[CAP];
__device__ unsigned int g_ncand;
__device__ unsigned int g_bin;

__global__ void reset_kernel() {
    int t = blockIdx.x * blockDim.x + threadIdx.x;
    for (int i = t; i < HBINS; i += gridDim.x * blockDim.x) g_hist[i] = 0u;
    if (t == 0) { g_ncand = 0u; g_bin = 0u; }
}

// Pass 1: NMS value per pixel + histogram (fused). Writes g_nms.
__global__ void nms_hist_kernel(const float* __restrict__ low,
                                const float* __restrict__ cur,
                                const float* __restrict__ high) {
    __shared__ unsigned int sh[HBINS];
    int lt  = threadIdx.y * blockDim.x + threadIdx.x;
    int nth = blockDim.x * blockDim.y;
    for (int i = lt; i < HBINS; i += nth) sh[i] = 0u;
    __syncthreads();

    int x = blockIdx.x * blockDim.x + threadIdx.x;
    int y = blockIdx.y * blockDim.y + threadIdx.y;
    float v = 0.0f;
    if (x >= 3 && x < WW - 3 && y >= 3 && y < HH - 3) {
        int idx = y * WW + x;
        float c = cur[idx];
        float m = c;
        #pragma unroll
        for (int dy = -1; dy <= 1; dy++) {
            #pragma unroll
            for (int dx = -1; dx <= 1; dx++) {
                m = fmaxf(m, cur[idx + dy * WW + dx]);
            }
        }
        // exact same float expression as reference: (cur - mp + 1e-5) > 0
        if ((c - m + NMS_EPS_F) > 0.0f && c > low[idx] && c > high[idx]) v = c;
    }
    g_nms[y * WW + x] = v;

    int b = (int)(v * (float)HBINS);
    if (b > HBINS - 1) b = HBINS - 1;
    if (b < 0) b = 0;
    atomicAdd(&sh[b], 1u);
    __syncthreads();
    for (int i = lt; i < HBINS; i += nth)
        if (sh[i]) atomicAdd(&g_hist[i], sh[i]);
}

// Pass 2: find max bin B such that count(values in bins >= B) >= k.
__global__ void thresh_kernel(int k) {
    __shared__ unsigned int suf[1024];
    int t = threadIdx.x;              // 1024 threads, 8 bins each
    unsigned int bins[8];
    unsigned int sum = 0;
    #pragma unroll
    for (int j = 0; j < 8; j++) { bins[j] = g_hist[t * 8 + j]; sum += bins[j]; }
    suf[t] = sum;
    __syncthreads();
    // Kogge-Stone inclusive suffix scan over chunk sums
    for (int off = 1; off < 1024; off <<= 1) {
        unsigned int add = (t + off < 1024) ? suf[t + off] : 0u;
        __syncthreads();
        suf[t] += add;
        __syncthreads();
    }
    unsigned int after = (t < 1023) ? suf[t + 1] : 0u;
    unsigned int acc = after;
    int best = -1;
    #pragma unroll
    for (int j = 7; j >= 0; j--) {
        acc += bins[j];                 // acc = count(bins >= t*8+j)
        if (acc >= (unsigned int)k) { best = t * 8 + j; break; }
    }
    if (best >= 0) atomicMax(&g_bin, (unsigned int)best);
}

// Pass 3: compact candidates with bin >= B into 64-bit sort keys.
// key = (value_bits << 32) | (0xFFFFFFFF - index)  -> sort desc gives
// value desc, index asc (XLA top_k tie semantics).
__global__ void compact_kernel() {
    unsigned int B = g_bin;
    int stride = gridDim.x * blockDim.x;
    int i0 = blockIdx.x * blockDim.x + threadIdx.x;
    const float4* p = (const float4*)g_nms;
    for (int i = i0; i < NPIX / 4; i += stride) {
        float4 q = p[i];
        float vs[4] = {q.x, q.y, q.z, q.w};
        #pragma unroll
        for (int j = 0; j < 4; j++) {
            int b = (int)(vs[j] * (float)HBINS);
            if (b > HBINS - 1) b = HBINS - 1;
            if (b < 0) b = 0;
            if ((unsigned int)b >= B) {
                unsigned int pos = atomicAdd(&g_ncand, 1u);
                if (pos < CAP) {
                    unsigned int idx = (unsigned int)(4 * i + j);
                    g_cand[pos] =
                        ((unsigned long long)__float_as_uint(vs[j]) << 32) |
                        (unsigned long long)(0xFFFFFFFFu - idx);
                }
            }
        }
    }
}

// Pass 4: one block sorts candidates (bitonic, descending), takes top-k,
// computes soft-argmax (3x3x3 correlation) and writes outputs.
extern __shared__ unsigned long long skeys[];
__global__ void final_kernel(const float* __restrict__ low,
                             const float* __restrict__ cur,
                             const float* __restrict__ high,
                             float* __restrict__ out, int k) {
    int t = threadIdx.x;
    int nt = blockDim.x;            // 1024
    unsigned int nc = g_ncand;
    if (nc > CAP) nc = CAP;
    for (int i = t; i < CAP; i += nt)
        skeys[i] = (i < (int)nc) ? g_cand[i] : 0ULL;
    __syncthreads();

    // bitonic sort descending over CAP (power of 2)
    for (int kk = 2; kk <= CAP; kk <<= 1) {
        for (int j = kk >> 1; j > 0; j >>= 1) {
            for (int i = t; i < CAP; i += nt) {
                int l = i ^ j;
                if (l > i) {
                    unsigned long long a = skeys[i];
                    unsigned long long b = skeys[l];
                    bool up = ((i & kk) == 0);
                    bool sw = up ? (a < b) : (a > b);
                    if (sw) { skeys[i] = b; skeys[l] = a; }
                }
            }
            __syncthreads();
        }
    }

    for (int i = t; i < k; i += nt) {
        unsigned long long key = skeys[i];
        float val = __uint_as_float((unsigned int)(key >> 32));
        unsigned int idx = 0xFFFFFFFFu - (unsigned int)(key & 0xFFFFFFFFu);
        out[i] = val;
        float a = 0.0f, fx = 0.0f, fy = 0.0f;
        if (idx < (unsigned int)NPIX) {
            int y = (int)(idx / WW);
            int x = (int)(idx % WW);
            float tot = 0.0f, sl = 0.0f, shh = 0.0f, wy = 0.0f, wx = 0.0f;
            #pragma unroll
            for (int dy = -1; dy <= 1; dy++) {
                #pragma unroll
                for (int dx = -1; dx <= 1; dx++) {
                    int jdx = (y + dy) * WW + (x + dx);
                    float lv = low[jdx];
                    float cv = cur[jdx];
                    float hv = high[jdx];
                    float s3 = lv + cv + hv;
                    tot += s3;
                    sl  += lv;
                    shh += hv;
                    wy  += (float)dy * s3;
                    wx  += (float)dx * s3;
                }
            }
            float den = tot + SAM_EPS_F;
            float s = (shh - sl) / den;
            fy = ((float)y + wy / den) * (1.0f / (float)HH);
            fx = ((float)x + wx / den) * (1.0f / (float)WW);
            a = s * (1.0f / 2048.0f);   // MR_SIZE / min(H,W) * s
        }
        float* o = out + k + 6 * i;     // full_A row-major [k,2,3]
        o[0] = a;    o[1] = 0.0f; o[2] = fx;
        o[3] = 0.0f; o[4] = a;    o[5] = fy;
    }
}

extern "C" void kernel_launch(void* const* d_in, const int* in_sizes, int n_in,
                              void* d_out, int out_size) {
    const float* low  = (const float*)d_in[0];
    const float* cur  = (const float*)d_in[1];
    const float* high = (const float*)d_in[2];
    float* out = (float*)d_out;
    int k = out_size / 7;   // out = [topk(k); full_A(k*6)]
    if (k < 1) k = 1;

    reset_kernel<<<8, 1024>>>();

    dim3 bb(32, 8);
    dim3 gg(WW / 32, HH / 8);
    nms_hist_kernel<<<gg, bb>>>(low, cur, high);

    thresh_kernel<<<1, 1024>>>(k);

    compact_kernel<<<2048, 256>>>();

    cudaFuncSetAttribute(final_kernel,
                         cudaFuncAttributeMaxDynamicSharedMemorySize,
                         CAP * (int)sizeof(unsigned long long));
    final_kernel<<<1, 1024, CAP * sizeof(unsigned long long)>>>(low, cur, high, out, k);
}